// round 16
// baseline (speedup 1.0000x reference)
#include <cuda_runtime.h>
#include <cstdint>
#include <cstddef>

// ---------------------------------------------------------------- constants
#define NB     128
#define NTOK   1369
#define DINOD  384
#define CLIPD  512
#define NH     8
#define HD     64
#define TN     32          // tokens per tile (triple-buffered)
#define NT     43          // ceil(1369/32); last tile has 25 valid tokens
#define DPITCH 388         // dino tile row pitch (floats): 16B-aligned
#define QPITCH 392         // qk row pitch (16B-aligned)
#define PSP    36          // p row pitch (36*4=144 B, 16B-aligned)

// dynamic smem layout for k_main (float offsets)
#define OFF_DS   0
#define OFF_QK   (3*TN*DPITCH)            // 37248
#define OFF_LP   (OFF_QK + NH*QPITCH)     // 40384
#define OFF_PS   (OFF_LP + 12*NH*TN)      // 43456
#define OFF_OUTS (OFF_PS + NH*PSP)        // 43744
#define OFF_MRUN (OFF_OUTS + CLIPD)       // 44256
#define OFF_LRUN (OFF_MRUN + NH)
#define OFF_ALPH (OFF_LRUN + NH)
#define OFF_RED  (OFF_ALPH + NH)
#define OFF_RED2 (OFF_RED + 12)
#define OFF_STAT (OFF_RED2 + 12)
#define SMEM_FLOATS (OFF_STAT + 2)
#define SMEM_BYTES  (SMEM_FLOATS * 4)     // ~177 KB

// packed fp32x2 ops (Blackwell FFMA2 — only reachable via PTX)
#define FMAF2(d, a, b) \
    asm("fma.rn.f32x2 %0, %1, %2, %0;" : "+l"(d) : "l"(a), "l"(b))
#define MULF2(d, a, b) \
    asm("mul.rn.f32x2 %0, %1, %2;" : "=l"(d) : "l"(a), "l"(b))
#define PACKF2(r, lo, hi) \
    asm("mov.b64 %0, {%1, %2};" : "=l"(r) : "f"(lo), "f"(hi))
#define UNPACKF2(lo, hi, r) \
    asm("mov.b64 {%0, %1}, %2;" : "=f"(lo), "=f"(hi) : "l"(r))

// device scratch (no allocation APIs allowed)
__device__ float g_qk[NB * NH * DINOD];

static __device__ __forceinline__ void cp16(float* sdst, const float* gsrc, bool valid) {
    uint32_t s = (uint32_t)__cvta_generic_to_shared(sdst);
    int sz = valid ? 16 : 0;     // sz=0 -> zero-fill destination
    asm volatile("cp.async.cg.shared.global [%0], [%1], 16, %2;\n"
                 :: "r"(s), "l"(gsrc), "r"(sz) : "memory");
}
static __device__ __forceinline__ void cpcommit() {
    asm volatile("cp.async.commit_group;\n" ::: "memory");
}

// ---------------------------------------------------------------------------
// Prep (measured 21.5us): per (b-group of 4, head) block
// ---------------------------------------------------------------------------
__global__ void __launch_bounds__(384)
k_prep(const float* __restrict__ clip, const float* __restrict__ Wq,
       const float* __restrict__ bq, const float* __restrict__ Wk,
       const float* __restrict__ temp) {
    __shared__ float clips[4 * CLIPD];     // 8 KB
    __shared__ float Wqs[2 * 64 * HD];     // 32 KB double buffer
    __shared__ float Qs[4 * HD];
    const int t  = threadIdx.x;
    const int bg = blockIdx.x;          // 0..31
    const int h  = blockIdx.y;          // 0..7

    #pragma unroll
    for (int i = t; i < 1024; i += 384) {
        int r = i >> 4, c4 = i & 15;
        cp16(&Wqs[r * HD + c4 * 4], Wq + (size_t)r * CLIPD + h * HD + c4 * 4, true);
    }
    cpcommit();
    for (int i = t; i < 4 * CLIPD; i += 384)
        clips[i] = clip[(bg * 4 + (i >> 9)) * CLIPD + (i & 511)];

    float q0 = 0.f, q1 = 0.f, q2 = 0.f, q3 = 0.f;
    const int bi = t >> 6, d = t & 63;            // valid for t < 256

    for (int kc = 0; kc < 8; ++kc) {
        if (kc + 1 < 8) {
            float* dst = &Wqs[((kc + 1) & 1) * 64 * HD];
            #pragma unroll
            for (int i = t; i < 1024; i += 384) {
                int r = i >> 4, c4 = i & 15;
                cp16(&dst[r * HD + c4 * 4],
                     Wq + (size_t)((kc + 1) * 64 + r) * CLIPD + h * HD + c4 * 4, true);
            }
            cpcommit();
            asm volatile("cp.async.wait_group 1;\n" ::: "memory");
        } else {
            asm volatile("cp.async.wait_group 0;\n" ::: "memory");
        }
        __syncthreads();
        if (t < 256) {
            const float* wb = &Wqs[(kc & 1) * 64 * HD];
            const float* cb = &clips[bi * CLIPD + kc * 64];
            #pragma unroll
            for (int k = 0; k < 64; k += 4) {
                q0 += cb[k]     * wb[(k)     * HD + d];
                q1 += cb[k + 1] * wb[(k + 1) * HD + d];
                q2 += cb[k + 2] * wb[(k + 2) * HD + d];
                q3 += cb[k + 3] * wb[(k + 3) * HD + d];
            }
        }
        __syncthreads();
    }
    if (t < 256) Qs[t] = q0 + q1 + q2 + q3 + bq[h * HD + d];
    __syncthreads();

    const float inv_scale = 1.0f / (8.0f * temp[0]);
    const int j = t;
    const float4* w4 = reinterpret_cast<const float4*>(Wk + (size_t)j * CLIPD + h * HD);
    const float4* q4 = reinterpret_cast<const float4*>(Qs);
    float a0 = 0.f, a1 = 0.f, a2 = 0.f, a3 = 0.f;
    #pragma unroll
    for (int i = 0; i < 16; ++i) {
        float4 w  = w4[i];
        float4 x0 = q4[i], x1 = q4[16 + i], x2 = q4[32 + i], x3 = q4[48 + i];
        a0 += w.x * x0.x + w.y * x0.y + w.z * x0.z + w.w * x0.w;
        a1 += w.x * x1.x + w.y * x1.y + w.z * x1.z + w.w * x1.w;
        a2 += w.x * x2.x + w.y * x2.y + w.z * x2.z + w.w * x2.w;
        a3 += w.x * x3.x + w.y * x3.y + w.z * x3.z + w.w * x3.w;
    }
    g_qk[((size_t)(bg * 4 + 0) * NH + h) * DINOD + j] = a0 * inv_scale;
    g_qk[((size_t)(bg * 4 + 1) * NH + h) * DINOD + j] = a1 * inv_scale;
    g_qk[((size_t)(bg * 4 + 2) * NH + h) * DINOD + j] = a2 * inv_scale;
    g_qk[((size_t)(bg * 4 + 3) * NH + h) * DINOD + j] = a3 * inv_scale;
}

// ---------------------------------------------------------------------------
// Main: per-b flash attention, software-pipelined [phase2(tt) | phase3(tt-1)]
// fused region + softmax per iter. grid = 128, 384 threads, triple buffer.
// ---------------------------------------------------------------------------
static __device__ __forceinline__ void issue_tile(const float* __restrict__ dino,
                                                  int b, int tile, float* dst, int t) {
    const int n0 = tile * TN;
    #pragma unroll
    for (int i = 0; i < 8; ++i) {
        int idx = t + i * 384;          // < 3072 = 32 rows * 96 float4
        int row = idx / 96;
        int c4  = idx % 96;
        int n   = n0 + row;
        bool valid = (n < NTOK);
        int nc = valid ? n : (NTOK - 1);                  // clamp addr, zfill data
        const float* src = dino + ((size_t)b * NTOK + nc) * DINOD + c4 * 4;
        cp16(dst + row * DPITCH + c4 * 4, src, valid);
    }
    cpcommit();
}

// phase3: rank-32 ctx update for one tile; thread owns column j = t
static __device__ __forceinline__ void phase3(const float* __restrict__ dsb,
                                              const float* __restrict__ ps,
                                              const float* __restrict__ alph,
                                              unsigned long long* ctx2, int t) {
    #pragma unroll
    for (int h = 0; h < NH; ++h) {
        float al = alph[h];
        unsigned long long aa;
        PACKF2(aa, al, al);
        MULF2(ctx2[h], ctx2[h], aa);
    }
    #pragma unroll
    for (int n4 = 0; n4 < 8; ++n4) {
        ulonglong2 p2[NH];
        #pragma unroll
        for (int h = 0; h < NH; ++h)
            p2[h] = *reinterpret_cast<const ulonglong2*>(&ps[h * PSP + n4 * 4]);
        float d0 = dsb[(n4 * 4 + 0) * DPITCH + t];
        float d1 = dsb[(n4 * 4 + 1) * DPITCH + t];
        float d2 = dsb[(n4 * 4 + 2) * DPITCH + t];
        float d3 = dsb[(n4 * 4 + 3) * DPITCH + t];
        unsigned long long dd01, dd23;
        PACKF2(dd01, d0, d1);
        PACKF2(dd23, d2, d3);
        #pragma unroll
        for (int h = 0; h < NH; ++h) {
            FMAF2(ctx2[h], p2[h].x, dd01);
            FMAF2(ctx2[h], p2[h].y, dd23);
        }
    }
}

__global__ void __launch_bounds__(384)
k_main(const float* __restrict__ dino, const float* __restrict__ Wv,
       const float* __restrict__ bv, const float* __restrict__ gamma,
       const float* __restrict__ beta, float* __restrict__ out) {
    extern __shared__ float sm[];
    const int b = blockIdx.x;
    const int t = threadIdx.x;
    const int w = t >> 5, l = t & 31;

    float* ds   = sm + OFF_DS;
    float* qks  = sm + OFF_QK;
    float* Lp   = sm + OFF_LP;
    float* ps   = sm + OFF_PS;
    float* outs = sm + OFF_OUTS;
    float* mrun = sm + OFF_MRUN;
    float* lrun = sm + OFF_LRUN;
    float* alph = sm + OFF_ALPH;
    float* red  = sm + OFF_RED;
    float* red2 = sm + OFF_RED2;
    float* stat = sm + OFF_STAT;

    for (int i = t; i < NH * DINOD; i += 384)
        qks[(i / DINOD) * QPITCH + (i % DINOD)] = g_qk[(size_t)b * NH * DINOD + i];
    if (t < NH) { mrun[t] = -3.0e38f; lrun[t] = 0.f; }

    unsigned long long ctx2[NH];
    #pragma unroll
    for (int h = 0; h < NH; ++h) ctx2[h] = 0ull;

    issue_tile(dino, b, 0, ds, t);

    // phase-2 decomposition: 16 n-groups (2 tokens) x 24 j-splits (16 j)
    const int gn = l & 15;
    const int gj = (w << 1) | (l >> 4);
    const int j0 = gj * 16;

    int cur = 0, prv = 2;   // triple-buffer indices (nxt = 3 - cur - prv when needed)

    for (int tt = 0; tt < NT; ++tt) {
        const int nxt = 3 - cur - prv;
        if (tt + 1 < NT) {
            issue_tile(dino, b, tt + 1, ds + nxt * TN * DPITCH, t);
            asm volatile("cp.async.wait_group 1;\n" ::: "memory");
        } else {
            asm volatile("cp.async.wait_group 0;\n" ::: "memory");
        }
        __syncthreads();   // ds(tt) visible; ps/alph(tt-1) from softmax visible

        const float* dsb = ds + cur * TN * DPITCH;

        // ---- fused region: phase2(tt) + phase3(tt-1) — dense ILP
        {
            unsigned long long acc2[NH][2];
            #pragma unroll
            for (int h = 0; h < NH; ++h) { acc2[h][0] = 0ull; acc2[h][1] = 0ull; }

            #pragma unroll
            for (int jj = 0; jj < 4; ++jj) {
                const int jc = j0 + jj * 4;
                ulonglong2 a2[NH];
                #pragma unroll
                for (int h = 0; h < NH; ++h)
                    a2[h] = *reinterpret_cast<const ulonglong2*>(&qks[h * QPITCH + jc]);
                #pragma unroll
                for (int k = 0; k < 2; ++k) {
                    ulonglong2 d2 = *reinterpret_cast<const ulonglong2*>(
                                        &dsb[(gn * 2 + k) * DPITCH + jc]);
                    #pragma unroll
                    for (int h = 0; h < NH; ++h) {
                        FMAF2(acc2[h][k], a2[h].x, d2.x);
                        FMAF2(acc2[h][k], a2[h].y, d2.y);
                    }
                }
            }
            if (tt > 0)
                phase3(ds + prv * TN * DPITCH, ps, alph, ctx2, t);

            #pragma unroll
            for (int h = 0; h < NH; ++h)
                #pragma unroll
                for (int k = 0; k < 2; ++k) {
                    float lo, hi;
                    UNPACKF2(lo, hi, acc2[h][k]);
                    float v = lo + hi;
                    v += __shfl_down_sync(0xffffffffu, v, 16);
                    if (l < 16) Lp[(w * NH + h) * TN + gn * 2 + k] = v;
                }
        }
        __syncthreads();   // Lp complete; phase3 reads of ds(prv) complete

        // ---- softmax(tt): warp h owns head h (32 tokens = full warp)
        if (w < NH) {
            const int h = w;
            const int valid = min(TN, NTOK - tt * TN);
            float v = -3.0e38f;
            if (l < valid) {
                float x = 0.f;
                #pragma unroll
                for (int s = 0; s < 12; ++s) x += Lp[(s * NH + h) * TN + l];
                v = x;
            }
            float m = v;
            #pragma unroll
            for (int o = 16; o > 0; o >>= 1)
                m = fmaxf(m, __shfl_xor_sync(0xffffffffu, m, o));
            float mold = mrun[h];
            float mnew = fmaxf(mold, m);
            float p = (l < valid) ? __expf(v - mnew) : 0.f;
            ps[h * PSP + l] = p;
            float s = p;
            #pragma unroll
            for (int o = 16; o > 0; o >>= 1)
                s += __shfl_xor_sync(0xffffffffu, s, o);
            if (l == 0) {
                float al = __expf(mold - mnew);
                alph[h] = al;
                lrun[h] = lrun[h] * al + s;
                mrun[h] = mnew;
            }
        }
        // rotate buffers (no barrier here; next-iter barrier orders softmax vs reads)
        prv = cur; cur = nxt;
    }
    __syncthreads();       // final ps/alph visible
    phase3(ds + prv * TN * DPITCH, ps, alph, ctx2, t);   // drain tile NT-1
    __syncthreads();

    // ---- epilogue: out = (ctx/l) @ Wv + bv, then LayerNorm
    #pragma unroll
    for (int h = 0; h < NH; ++h) {
        float lo, hi;
        UNPACKF2(lo, hi, ctx2[h]);
        sm[h * DPITCH + t] = (lo + hi) / lrun[h];   // ctx overlays ds buffer
    }
    __syncthreads();

    for (int c = t; c < CLIPD; c += 384) {
        const int h = c >> 6;
        const float* crow = sm + h * DPITCH;
        const float* wcol = Wv + c;
        float a0 = 0.f, a1 = 0.f, a2 = 0.f, a3 = 0.f;
        #pragma unroll 4
        for (int jx = 0; jx < DINOD; jx += 4) {
            a0 += crow[jx]     * wcol[(size_t)jx * CLIPD];
            a1 += crow[jx + 1] * wcol[(size_t)(jx + 1) * CLIPD];
            a2 += crow[jx + 2] * wcol[(size_t)(jx + 2) * CLIPD];
            a3 += crow[jx + 3] * wcol[(size_t)(jx + 3) * CLIPD];
        }
        outs[c] = a0 + a1 + a2 + a3 + bv[c];
    }
    __syncthreads();

    float s = 0.f, s2 = 0.f;
    for (int c = t; c < CLIPD; c += 384) { float v = outs[c]; s += v; s2 += v * v; }
    #pragma unroll
    for (int o = 16; o > 0; o >>= 1) {
        s  += __shfl_xor_sync(0xffffffffu, s, o);
        s2 += __shfl_xor_sync(0xffffffffu, s2, o);
    }
    if (l == 0) { red[w] = s; red2[w] = s2; }
    __syncthreads();
    if (t == 0) {
        float ss = 0.f, ss2 = 0.f;
        for (int i = 0; i < 12; ++i) { ss += red[i]; ss2 += red2[i]; }
        float mu  = ss / 512.f;
        float var = ss2 / 512.f - mu * mu;
        stat[0] = mu;
        stat[1] = rsqrtf(var + 1e-5f);
    }
    __syncthreads();
    float mu = stat[0], rs = stat[1];
    for (int c = t; c < CLIPD; c += 384)
        out[(size_t)b * CLIPD + c] = (outs[c] - mu) * rs * gamma[c] + beta[c];
}

// ---------------------------------------------------------------------------
extern "C" void kernel_launch(void* const* d_in, const int* in_sizes, int n_in,
                              void* d_out, int out_size) {
    const float* dino  = (const float*)d_in[0];
    const float* clip  = (const float*)d_in[1];
    const float* Wq    = (const float*)d_in[2];
    const float* bq    = (const float*)d_in[3];
    const float* Wk    = (const float*)d_in[4];
    // d_in[5] = bk: cancels in softmax (constant per (b,h))
    const float* Wv    = (const float*)d_in[6];
    const float* bv    = (const float*)d_in[7];
    const float* temp  = (const float*)d_in[8];
    const float* gamma = (const float*)d_in[9];
    const float* beta  = (const float*)d_in[10];
    float* out = (float*)d_out;
    (void)in_sizes; (void)n_in; (void)out_size;

    cudaFuncSetAttribute(k_main, cudaFuncAttributeMaxDynamicSharedMemorySize, SMEM_BYTES);

    k_prep<<<dim3(32, 8), 384>>>(clip, Wq, bq, Wk, temp);
    k_main<<<NB, 384, SMEM_BYTES>>>(dino, Wv, bv, gamma, beta, out);
}